// round 1
// baseline (speedup 1.0000x reference)
#include <cuda_runtime.h>
#include <stdint.h>

#define CCH 128          // channels
#define XSTRIDE 132      // padded smem row stride (floats)
#define THREADS 256
#define TILE_P 128       // conv positions per CTA
#define TILE_J 64        // pooled outputs per CTA
#define CHUNK 16         // k-chunk of input channels staged in smem

// ---- scratch (no allocations allowed) ----
__device__ float g_W0[CCH * CCH];     // [c][o] = W[o, c, 0]
__device__ float g_W1[CCH * CCH];     // [c][o] = W[o, c, 1]
__device__ float g_bias[32 * CCH];    // per-level effective bias
__device__ float g_bufA[262144 * 128];  // even-level outputs (max 262143 rows)
__device__ float g_bufB[131072 * 128];  // odd-level outputs  (max 131071 rows)

// packed fp32x2 helpers (Blackwell dual-rate fp32)
#define FMA2(d, a, bb) asm("fma.rn.f32x2 %0, %1, %2, %0;" : "+l"(d) : "l"(a), "l"(bb))
#define PACK2(d, s)    asm("mov.b64 %0, {%1, %1};" : "=l"(d) : "f"(s))
#define UNPACK2(lo, hi, s) asm("mov.b64 {%0, %1}, %2;" : "=f"(lo), "=f"(hi) : "l"(s))

// ---------------------------------------------------------------------------
// Precompute: weight re-layout + per-level bias (depth channels are constant
// per level, so their conv contribution folds into a bias vector).
// ---------------------------------------------------------------------------
__global__ void precompute_kernel(const float* __restrict__ W,
                                  const float* __restrict__ b,
                                  const float* __restrict__ depth,
                                  int nlev) {
    int tid = threadIdx.x;
    // W layout: [o][i][k], i in [0,256), k in {0,1}; strides (512, 2, 1)
    for (int i = tid; i < CCH * CCH; i += blockDim.x) {
        int c = i >> 7, o = i & 127;
        g_W0[c * CCH + o] = W[(size_t)o * 512 + c * 2 + 0];
        g_W1[c * CCH + o] = W[(size_t)o * 512 + c * 2 + 1];
    }
    if (tid < CCH) {
        int o = tid;
        float ws[CCH];
        #pragma unroll 4
        for (int c = 0; c < CCH; ++c)
            ws[c] = W[(size_t)o * 512 + (128 + c) * 2 + 0] +
                    W[(size_t)o * 512 + (128 + c) * 2 + 1];
        for (int lev = 0; lev < nlev; ++lev) {
            float s = b[o];
            #pragma unroll 4
            for (int c = 0; c < CCH; ++c) s += ws[c] * depth[lev * CCH + c];
            g_bias[lev * CCH + o] = s;
        }
    }
}

// ---------------------------------------------------------------------------
// One level: z[o,l] = A0 x_l + A1 x_{l+1} + bias; leaky(0.2); maxpool(2,2).
// CTA: all 128 out-channels x 128 conv positions (=64 pooled outputs).
// Thread: 8 o (4 f32x2 pairs) x 8 p.
// Level 0 gathers input rows through perm.
// ---------------------------------------------------------------------------
__global__ __launch_bounds__(THREADS, 2)
void level_kernel(const float* __restrict__ Xin,
                  const int* __restrict__ perm,   // non-null only for level 0
                  float* __restrict__ Yout,
                  int Lin, int Lout, int level) {
    extern __shared__ float smem[];
    float* sW0 = smem;                     // CHUNK*CCH
    float* sW1 = smem + CHUNK * CCH;       // CHUNK*CCH
    float* Xs  = smem + 2 * CHUNK * CCH;   // CCH * XSTRIDE, layout [c][p]

    const int tid = threadIdx.x;
    const int og = tid & 15, pg = tid >> 4;
    const int o0 = og * 8, p0 = pg * 8;
    const int pbase = blockIdx.x * TILE_P;

    // Load 129 input positions x 128 channels, transposed into Xs[c][p].
    // Clamped out-of-range positions only feed invalid (unstored) outputs.
    for (int i = tid; i < 129 * 32; i += THREADS) {
        int p  = i >> 5;
        int c4 = i & 31;
        int pin = pbase + p;
        if (pin > Lin - 1) pin = Lin - 1;
        const float4* src;
        if (perm) src = (const float4*)(Xin + (size_t)perm[pin] * CCH) + c4;
        else      src = (const float4*)(Xin + (size_t)pin * CCH) + c4;
        float4 v = *src;
        int c = c4 * 4;
        Xs[(c + 0) * XSTRIDE + p] = v.x;
        Xs[(c + 1) * XSTRIDE + p] = v.y;
        Xs[(c + 2) * XSTRIDE + p] = v.z;
        Xs[(c + 3) * XSTRIDE + p] = v.w;
    }

    unsigned long long acc[4][8];
    #pragma unroll
    for (int a = 0; a < 4; ++a)
        #pragma unroll
        for (int p = 0; p < 8; ++p) acc[a][p] = 0ull;

    for (int cc = 0; cc < CCH; cc += CHUNK) {
        __syncthreads();   // also covers Xs visibility on first iteration
        {
            const float4* w0src = (const float4*)(g_W0 + cc * CCH);
            const float4* w1src = (const float4*)(g_W1 + cc * CCH);
            float4* d0 = (float4*)sW0;
            float4* d1 = (float4*)sW1;
            for (int i = tid; i < (CHUNK * CCH) / 4; i += THREADS) {
                d0[i] = w0src[i];
                d1[i] = w1src[i];
            }
        }
        __syncthreads();

        #pragma unroll 4
        for (int c = 0; c < CHUNK; ++c) {
            const float* xr = &Xs[(cc + c) * XSTRIDE + p0];
            float4 xa = *(const float4*)xr;
            float4 xb = *(const float4*)(xr + 4);
            float x8 = xr[8];
            unsigned long long xx[9];
            PACK2(xx[0], xa.x); PACK2(xx[1], xa.y);
            PACK2(xx[2], xa.z); PACK2(xx[3], xa.w);
            PACK2(xx[4], xb.x); PACK2(xx[5], xb.y);
            PACK2(xx[6], xb.z); PACK2(xx[7], xb.w);
            PACK2(xx[8], x8);

            ulonglong2 w0a = *(const ulonglong2*)&sW0[c * CCH + o0];
            ulonglong2 w0b = *(const ulonglong2*)&sW0[c * CCH + o0 + 4];
            ulonglong2 w1a = *(const ulonglong2*)&sW1[c * CCH + o0];
            ulonglong2 w1b = *(const ulonglong2*)&sW1[c * CCH + o0 + 4];
            unsigned long long w0[4] = {w0a.x, w0a.y, w0b.x, w0b.y};
            unsigned long long w1[4] = {w1a.x, w1a.y, w1b.x, w1b.y};

            #pragma unroll
            for (int a = 0; a < 4; ++a) {
                #pragma unroll
                for (int p = 0; p < 8; ++p) {
                    FMA2(acc[a][p], w0[a], xx[p]);
                    FMA2(acc[a][p], w1[a], xx[p + 1]);
                }
            }
        }
    }

    // Epilogue: bias + leaky(0.2) + pool pairs, store [Lout][128].
    const int jb = blockIdx.x * TILE_J + pg * 4;
    float res[4][8];   // [j][o_local]
    #pragma unroll
    for (int a = 0; a < 4; ++a) {
        float2 bias2 = *(const float2*)&g_bias[level * CCH + o0 + a * 2];
        #pragma unroll
        for (int j = 0; j < 4; ++j) {
            float zl0, zh0, zl1, zh1;
            UNPACK2(zl0, zh0, acc[a][2 * j]);
            UNPACK2(zl1, zh1, acc[a][2 * j + 1]);
            zl0 += bias2.x; zh0 += bias2.y;
            zl1 += bias2.x; zh1 += bias2.y;
            zl0 = zl0 >= 0.f ? zl0 : 0.2f * zl0;
            zh0 = zh0 >= 0.f ? zh0 : 0.2f * zh0;
            zl1 = zl1 >= 0.f ? zl1 : 0.2f * zl1;
            zh1 = zh1 >= 0.f ? zh1 : 0.2f * zh1;
            res[j][a * 2 + 0] = fmaxf(zl0, zl1);
            res[j][a * 2 + 1] = fmaxf(zh0, zh1);
        }
    }
    #pragma unroll
    for (int j = 0; j < 4; ++j) {
        if (jb + j < Lout) {
            float4* dst = (float4*)(Yout + (size_t)(jb + j) * CCH + o0);
            dst[0] = make_float4(res[j][0], res[j][1], res[j][2], res[j][3]);
            dst[1] = make_float4(res[j][4], res[j][5], res[j][6], res[j][7]);
        }
    }
}

// ---------------------------------------------------------------------------
extern "C" void kernel_launch(void* const* d_in, const int* in_sizes, int n_in,
                              void* d_out, int out_size) {
    const float* x     = (const float*)d_in[0];
    const float* depth = (const float*)d_in[1];
    const float* W     = (const float*)d_in[2];
    const float* b     = (const float*)d_in[3];
    const int*   perm  = (const int*)d_in[4];
    float* out = (float*)d_out;

    int N = in_sizes[0] / CCH;

    int nlev = 0;
    { int L = N; while (L > 1) { L = (L - 1) / 2; nlev++; } }

    size_t smem_bytes = (size_t)(2 * CHUNK * CCH + CCH * XSTRIDE) * sizeof(float);
    cudaFuncSetAttribute((const void*)level_kernel,
                         cudaFuncAttributeMaxDynamicSharedMemorySize,
                         (int)smem_bytes);

    precompute_kernel<<<1, 256>>>(W, b, depth, nlev);

    float *bufA, *bufB;
    cudaGetSymbolAddress((void**)&bufA, g_bufA);
    cudaGetSymbolAddress((void**)&bufB, g_bufB);

    const float* cur = x;
    const int* permArg = perm;
    int L = N, level = 0;
    while (L > 1) {
        int Lout = (L - 1) / 2;
        float* dst = (Lout == 1) ? out : ((level & 1) ? bufB : bufA);
        int grid = (Lout + TILE_J - 1) / TILE_J;
        level_kernel<<<grid, THREADS, smem_bytes>>>(cur, permArg, dst, L, Lout, level);
        permArg = nullptr;
        cur = dst;
        L = Lout;
        level++;
    }
}

// round 3
// speedup vs baseline: 1.9800x; 1.9800x over previous
#include <cuda_runtime.h>
#include <cuda_bf16.h>
#include <stdint.h>

#define CCH 128
#define THREADS 256

// ---- device scratch ----
__device__ float    g_bias[32 * CCH];
__device__ uint32_t g_Wtm[2][CCH][128];     // [hi/lo][o][k/2] bf16x2 of Acat=[W0 W1]
__device__ float    g_bufA[262144 * 128];
__device__ float    g_bufB[131072 * 128];

// ---- SMEM layout ----
#define SM_XH 0
#define SM_XL 33024
#define SM_WH 66048
#define SM_WL 131584
#define SM_TOT 197120

__device__ __forceinline__ uint32_t smem_u32(const void* p) {
    uint32_t a;
    asm("{ .reg .u64 t; cvta.to.shared.u64 t, %1; cvt.u32.u64 %0, t; }" : "=r"(a) : "l"(p));
    return a;
}
__device__ __forceinline__ void ldx4(uint32_t& r0, uint32_t& r1, uint32_t& r2, uint32_t& r3,
                                     uint32_t addr) {
    asm volatile("ldmatrix.sync.aligned.m8n8.x4.shared.b16 {%0,%1,%2,%3}, [%4];"
                 : "=r"(r0), "=r"(r1), "=r"(r2), "=r"(r3) : "r"(addr));
}
__device__ __forceinline__ void mma_bf16(float* d, const uint32_t* a, const uint32_t* b) {
    asm volatile("mma.sync.aligned.m16n8k16.row.col.f32.bf16.bf16.f32 "
                 "{%0,%1,%2,%3}, {%4,%5,%6,%7}, {%8,%9}, {%0,%1,%2,%3};"
                 : "+f"(d[0]), "+f"(d[1]), "+f"(d[2]), "+f"(d[3])
                 : "r"(a[0]), "r"(a[1]), "r"(a[2]), "r"(a[3]), "r"(b[0]), "r"(b[1]));
}
#define STS64(addr, x, y) \
    asm volatile("st.shared.v2.u32 [%0], {%1,%2};" :: "r"(addr), "r"(x), "r"(y) : "memory")

// ---------------------------------------------------------------------------
__global__ void precompute_kernel(const float* __restrict__ W,
                                  const float* __restrict__ b,
                                  const float* __restrict__ depth,
                                  int nlev) {
    int tid = threadIdx.x;
    for (int i = tid; i < 2 * CCH * 128; i += blockDim.x) {
        int s = i >> 14, o = (i >> 7) & 127, col = i & 127;
        uint32_t out = 0;
        #pragma unroll
        for (int h = 0; h < 2; ++h) {
            int c = 2 * col + h;
            float w = (c < 128) ? W[(size_t)o * 512 + c * 2]
                                : W[(size_t)o * 512 + (c - 128) * 2 + 1];
            __nv_bfloat16 hi = __float2bfloat16_rn(w);
            __nv_bfloat16 v = (s == 0) ? hi
                              : __float2bfloat16_rn(w - __bfloat162float(hi));
            uint16_t bits = *(uint16_t*)&v;
            out |= (uint32_t)bits << (16 * h);
        }
        g_Wtm[s][o][col] = out;
    }
    if (tid < CCH) {
        int o = tid;
        float ws[CCH];
        #pragma unroll 4
        for (int c = 0; c < CCH; ++c)
            ws[c] = W[(size_t)o * 512 + (128 + c) * 2 + 0] +
                    W[(size_t)o * 512 + (128 + c) * 2 + 1];
        for (int lev = 0; lev < nlev; ++lev) {
            float s = b[o];
            #pragma unroll 4
            for (int c = 0; c < CCH; ++c) s += ws[c] * depth[lev * CCH + c];
            g_bias[lev * CCH + o] = s;
        }
    }
}

// ---------------------------------------------------------------------------
// GEMM per level tile: D[p=128, o=128] = Xcat[p, K=256] * Wcat[o, K=256]^T
// via mma.m16n8k16 bf16 (3 split products). 8 warps: 2(m)x4(n), warp 64x32.
// Xcat virtual: k<128 -> X[p][k], k>=128 -> X[p+1][k-128].
// Epilogue: +bias, leaky(0.2), maxpool(2,2) via shfl, store [Lout][128].
// Handles nlev levels in sequence (grid must be 1 unless nlev==1).
// ---------------------------------------------------------------------------
__global__ __launch_bounds__(THREADS, 1)
void level_kernel(const float* __restrict__ Xin, const int* __restrict__ perm,
                  float* bufA, float* bufB, float* outp,
                  int Lin, int level0, int nlev) {
    extern __shared__ char smem[];
    const uint32_t sb = smem_u32(smem);
    const int tid = threadIdx.x, l = tid & 31, wid = tid >> 5;
    const int wm = (wid >> 2) * 64, wn = (wid & 3) * 32;

    // ---- W -> smem once (swizzled, rows o of 512B) ----
    for (int i = tid; i < 2 * 128 * 64; i += THREADS) {
        int split = i >> 13, rem = i & 8191, o = rem >> 6, u = rem & 63;
        uint2 v = ((const uint2*)&g_Wtm[split][o][0])[u];
        uint32_t byte = (uint32_t)o * 512 + (((uint32_t)u * 8) ^ (uint32_t)((o & 7) << 4));
        STS64(sb + (split ? SM_WL : SM_WH) + byte, v.x, v.y);
    }

    // ---- per-lane fragment address precompute ----
    const int arl = ((l >> 3) & 1) * 8 + (l & 7);
    uint32_t aRow[4][2], aS[4][2];
    #pragma unroll
    for (int mt = 0; mt < 4; ++mt)
        #pragma unroll
        for (int tap = 0; tap < 2; ++tap) {
            int row = wm + mt * 16 + arl + tap;
            aRow[mt][tap] = (uint32_t)row * 256;
            aS[mt][tap] = (uint32_t)((row & 7) << 4);
        }
    uint32_t bRow[2], bS[2];
    #pragma unroll
    for (int g = 0; g < 2; ++g) {
        int o = wn + g * 16 + ((l >> 4) & 1) * 8 + (l & 7);
        bRow[g] = (uint32_t)o * 512;
        bS[g] = (uint32_t)((o & 7) << 4);
    }
    const uint32_t a_k8b = ((l >> 4) & 1) * 16;
    const uint32_t b_k8b = ((l >> 3) & 1) * 16;

    const float* Xcur = Xin;
    const int* pm = (level0 == 0) ? perm : nullptr;
    int L = Lin, lvl = level0;

    for (int s = 0; s < nlev; ++s) {
        const int Lout = (L - 1) >> 1;
        float* Yout = (Lout == 1) ? outp : ((lvl & 1) ? bufB : bufA);
        const int ntiles = (Lout + 63) >> 6;
        const float2 bias2 = *(const float2*)&g_bias[lvl * CCH + wn + (l & 3) * 2];

        for (int tile = blockIdx.x; tile < ntiles; tile += gridDim.x) {
            const int pbase = tile << 7;
            __syncthreads();   // protect X smem (prev tile reads / prev level stores)

            // ---- load X tile: 129 rows x 128 ch, split bf16 hi/lo ----
            for (int i = tid; i < 129 * 32; i += THREADS) {
                int row = i >> 5, c4 = i & 31;
                int pin = pbase + row; if (pin > L - 1) pin = L - 1;
                size_t srow = pm ? (size_t)pm[pin] : (size_t)pin;
                float4 v = *((const float4*)(Xcur + srow * CCH) + c4);
                __nv_bfloat16 h0 = __float2bfloat16_rn(v.x), h1 = __float2bfloat16_rn(v.y);
                __nv_bfloat16 h2 = __float2bfloat16_rn(v.z), h3 = __float2bfloat16_rn(v.w);
                __nv_bfloat16 l0 = __float2bfloat16_rn(v.x - __bfloat162float(h0));
                __nv_bfloat16 l1 = __float2bfloat16_rn(v.y - __bfloat162float(h1));
                __nv_bfloat16 l2 = __float2bfloat16_rn(v.z - __bfloat162float(h2));
                __nv_bfloat16 l3 = __float2bfloat16_rn(v.w - __bfloat162float(h3));
                __nv_bfloat162 hp0 = {h0, h1}, hp1 = {h2, h3};
                __nv_bfloat162 lp0 = {l0, l1}, lp1 = {l2, l3};
                uint32_t byte = (uint32_t)row * 256 +
                                (((uint32_t)c4 * 8) ^ (uint32_t)((row & 7) << 4));
                STS64(sb + SM_XH + byte, *(uint32_t*)&hp0, *(uint32_t*)&hp1);
                STS64(sb + SM_XL + byte, *(uint32_t*)&lp0, *(uint32_t*)&lp1);
            }
            __syncthreads();

            // ---- MMA: 3 products (Xh*Wh, Xl*Wh, Xh*Wl), K=256 each ----
            float acc[4][4][4];
            #pragma unroll
            for (int mt = 0; mt < 4; ++mt)
                #pragma unroll
                for (int nt = 0; nt < 4; ++nt)
                    #pragma unroll
                    for (int r = 0; r < 4; ++r) acc[mt][nt][r] = 0.f;

            #pragma unroll 1
            for (int prod = 0; prod < 3; ++prod) {
                const uint32_t xb = sb + (prod == 1 ? SM_XL : SM_XH);
                const uint32_t wb = sb + (prod == 2 ? SM_WL : SM_WH);
                #pragma unroll
                for (int kt = 0; kt < 16; ++kt) {
                    const int tap = kt >> 3;
                    const uint32_t chA = (uint32_t)(kt & 7) * 32 + a_k8b;
                    const uint32_t chB = (uint32_t)kt * 32 + b_k8b;
                    uint32_t B[4][2];
                    ldx4(B[0][0], B[0][1], B[1][0], B[1][1], wb + bRow[0] + (chB ^ bS[0]));
                    ldx4(B[2][0], B[2][1], B[3][0], B[3][1], wb + bRow[1] + (chB ^ bS[1]));
                    #pragma unroll
                    for (int mt = 0; mt < 4; ++mt) {
                        uint32_t A[4];
                        ldx4(A[0], A[1], A[2], A[3],
                             xb + aRow[mt][tap] + (chA ^ aS[mt][tap]));
                        #pragma unroll
                        for (int nt = 0; nt < 4; ++nt)
                            mma_bf16(acc[mt][nt], A, B[nt]);
                    }
                }
            }

            // ---- epilogue: bias + leaky + pool(2) + store ----
            const int r2 = l >> 2;
            const bool storer = ((r2 & 1) == 0);
            const int jbase = tile << 6;
            #pragma unroll
            for (int mt = 0; mt < 4; ++mt)
                #pragma unroll
                for (int nt = 0; nt < 4; ++nt) {
                    float* d = acc[mt][nt];
                    // bias for this nt: shift by nt*8 channels
                    float bx, by;
                    if (nt == 0) { bx = bias2.x; by = bias2.y; }
                    else {
                        const float2 bb =
                            *(const float2*)&g_bias[lvl * CCH + wn + nt * 8 + (l & 3) * 2];
                        bx = bb.x; by = bb.y;
                    }
                    float v0 = d[0] + bx, v1 = d[1] + by;
                    float v2 = d[2] + bx, v3 = d[3] + by;
                    v0 = v0 >= 0.f ? v0 : 0.2f * v0;
                    v1 = v1 >= 0.f ? v1 : 0.2f * v1;
                    v2 = v2 >= 0.f ? v2 : 0.2f * v2;
                    v3 = v3 >= 0.f ? v3 : 0.2f * v3;
                    float u0 = fmaxf(v0, __shfl_xor_sync(0xffffffffu, v0, 4));
                    float u1 = fmaxf(v1, __shfl_xor_sync(0xffffffffu, v1, 4));
                    float u2 = fmaxf(v2, __shfl_xor_sync(0xffffffffu, v2, 4));
                    float u3 = fmaxf(v3, __shfl_xor_sync(0xffffffffu, v3, 4));
                    if (storer) {
                        const int o0 = wn + nt * 8 + (l & 3) * 2;
                        const int jl = jbase + ((wm + mt * 16 + r2) >> 1);
                        const int jh = jl + 4;
                        if (jl < Lout)
                            *(float2*)&Yout[(size_t)jl * CCH + o0] = make_float2(u0, u1);
                        if (jh < Lout)
                            *(float2*)&Yout[(size_t)jh * CCH + o0] = make_float2(u2, u3);
                    }
                }
        }
        Xcur = Yout;
        L = Lout;
        lvl++;
        pm = nullptr;
    }
}

// ---------------------------------------------------------------------------
extern "C" void kernel_launch(void* const* d_in, const int* in_sizes, int n_in,
                              void* d_out, int out_size) {
    const float* x     = (const float*)d_in[0];
    const float* depth = (const float*)d_in[1];
    const float* W     = (const float*)d_in[2];
    const float* b     = (const float*)d_in[3];
    const int*   perm  = (const int*)d_in[4];
    float* out = (float*)d_out;

    int N = in_sizes[0] / CCH;
    int nlev = 0;
    { int L = N; while (L > 1) { L = (L - 1) / 2; nlev++; } }

    cudaFuncSetAttribute((const void*)level_kernel,
                         cudaFuncAttributeMaxDynamicSharedMemorySize, SM_TOT);

    precompute_kernel<<<1, 256>>>(W, b, depth, nlev);

    float *bufA, *bufB;
    cudaGetSymbolAddress((void**)&bufA, g_bufA);
    cudaGetSymbolAddress((void**)&bufB, g_bufB);

    const float* cur = x;
    const int* permArg = perm;
    int L = N, level = 0;
    while (L > 1) {
        if (L <= 127) {
            int rem = 0;
            { int t = L; while (t > 1) { t = (t - 1) / 2; rem++; } }
            level_kernel<<<1, THREADS, SM_TOT>>>((const float*)cur, nullptr,
                                                 bufA, bufB, out, L, level, rem);
            break;
        }
        int Lout = (L - 1) / 2;
        int ntiles = (Lout + 63) / 64;
        int grid = ntiles < 152 ? ntiles : 152;
        level_kernel<<<grid, THREADS, SM_TOT>>>((const float*)cur, permArg,
                                                bufA, bufB, out, L, level, 1);
        permArg = nullptr;
        cur = (Lout == 1) ? out : ((level & 1) ? bufB : bufA);
        L = Lout;
        level++;
    }
}

// round 4
// speedup vs baseline: 2.0113x; 1.0158x over previous
#include <cuda_runtime.h>
#include <cuda_bf16.h>
#include <stdint.h>

#define CCH 128
#define THREADS 256
#define GRIDMAX 152

// ---- device scratch ----
__device__ float    g_bias[32 * CCH];
__device__ uint32_t g_Wtm[2][CCH][128];     // [hi/lo][o][k/2] bf16x2 of Acat=[W0 W1]
__device__ float    g_bufA[262144 * 128];
__device__ float    g_bufB[131072 * 128];

// ---- SMEM layout (bytes) ----
#define SM_XH 0                 // X hi: 129 rows x 256B  (also reused as stage)
#define SM_XL 33024             // X lo: 129 rows x 256B
#define SM_WH 66048             // W hi: 128 rows x 512B
#define SM_WL 131584            // W lo
#define SM_TOT 197120
#define STAGE_STRIDE 136        // floats per staged row (544B; +8 banks/row)

__device__ __forceinline__ uint32_t smem_u32(const void* p) {
    uint32_t a;
    asm("{ .reg .u64 t; cvta.to.shared.u64 t, %1; cvt.u32.u64 %0, t; }" : "=r"(a) : "l"(p));
    return a;
}
__device__ __forceinline__ void ldx4(uint32_t& r0, uint32_t& r1, uint32_t& r2, uint32_t& r3,
                                     uint32_t addr) {
    asm volatile("ldmatrix.sync.aligned.m8n8.x4.shared.b16 {%0,%1,%2,%3}, [%4];"
                 : "=r"(r0), "=r"(r1), "=r"(r2), "=r"(r3) : "r"(addr));
}
__device__ __forceinline__ void mma_bf16(float* d, const uint32_t* a, const uint32_t* b) {
    asm volatile("mma.sync.aligned.m16n8k16.row.col.f32.bf16.bf16.f32 "
                 "{%0,%1,%2,%3}, {%4,%5,%6,%7}, {%8,%9}, {%0,%1,%2,%3};"
                 : "+f"(d[0]), "+f"(d[1]), "+f"(d[2]), "+f"(d[3])
                 : "r"(a[0]), "r"(a[1]), "r"(a[2]), "r"(a[3]), "r"(b[0]), "r"(b[1]));
}
#define STS64(addr, x, y) \
    asm volatile("st.shared.v2.u32 [%0], {%1,%2};" :: "r"(addr), "r"(x), "r"(y) : "memory")

// ---------------------------------------------------------------------------
__global__ void precompute_kernel(const float* __restrict__ W,
                                  const float* __restrict__ b,
                                  const float* __restrict__ depth,
                                  int nlev) {
    int tid = threadIdx.x;
    for (int i = tid; i < 2 * CCH * 128; i += blockDim.x) {
        int s = i >> 14, o = (i >> 7) & 127, col = i & 127;
        uint32_t out = 0;
        #pragma unroll
        for (int h = 0; h < 2; ++h) {
            int c = 2 * col + h;
            float w = (c < 128) ? W[(size_t)o * 512 + c * 2]
                                : W[(size_t)o * 512 + (c - 128) * 2 + 1];
            __nv_bfloat16 hi = __float2bfloat16_rn(w);
            __nv_bfloat16 v = (s == 0) ? hi
                              : __float2bfloat16_rn(w - __bfloat162float(hi));
            uint16_t bits = *(uint16_t*)&v;
            out |= (uint32_t)bits << (16 * h);
        }
        g_Wtm[s][o][col] = out;
    }
    if (tid < CCH) {
        int o = tid;
        float ws[CCH];
        #pragma unroll 4
        for (int c = 0; c < CCH; ++c)
            ws[c] = W[(size_t)o * 512 + (128 + c) * 2 + 0] +
                    W[(size_t)o * 512 + (128 + c) * 2 + 1];
        for (int lev = 0; lev < nlev; ++lev) {
            float s = b[o];
            #pragma unroll 4
            for (int c = 0; c < CCH; ++c) s += ws[c] * depth[lev * CCH + c];
            g_bias[lev * CCH + o] = s;
        }
    }
}

// ---------------------------------------------------------------------------
// D[p=128, o=128] = Xcat[p, K=256] * Wcat[o, K=256]^T, bf16 split-2, 3 products
// issued inside ONE kt loop (fragments reused). Epilogue: bias + leaky(0.2) +
// maxpool(2,2) via shfl -> smem stage -> coalesced STG.128.
// ---------------------------------------------------------------------------
__global__ __launch_bounds__(THREADS, 1)
void level_kernel(const float* __restrict__ Xin, const int* __restrict__ perm,
                  float* bufA, float* bufB, float* outp,
                  int Lin, int level0, int nlev) {
    extern __shared__ char smem[];
    const uint32_t sb = smem_u32(smem);
    float* stagef = (float*)smem;                  // reuses X region post-MMA
    const int tid = threadIdx.x, l = tid & 31, wid = tid >> 5;
    const int wm = (wid >> 2) * 64, wn = (wid & 3) * 32;

    // ---- W -> smem once (swizzled rows of 512B) ----
    for (int i = tid; i < 2 * 128 * 64; i += THREADS) {
        int split = i >> 13, rem = i & 8191, o = rem >> 6, u = rem & 63;
        uint2 v = ((const uint2*)&g_Wtm[split][o][0])[u];
        uint32_t byte = (uint32_t)o * 512 + (((uint32_t)u * 8) ^ (uint32_t)((o & 7) << 4));
        STS64(sb + (split ? SM_WL : SM_WH) + byte, v.x, v.y);
    }

    // ---- per-lane fragment addresses ----
    const int arl = ((l >> 3) & 1) * 8 + (l & 7);
    uint32_t aAddr[4][2];   // [mt][tap] base (row*256 part), swizzle applied at use
    uint32_t aS[4][2];
    #pragma unroll
    for (int mt = 0; mt < 4; ++mt)
        #pragma unroll
        for (int tap = 0; tap < 2; ++tap) {
            int row = wm + mt * 16 + arl + tap;
            aAddr[mt][tap] = (uint32_t)row * 256;
            aS[mt][tap] = (uint32_t)((row & 7) << 4);
        }
    uint32_t bRow[2], bS[2];
    #pragma unroll
    for (int g = 0; g < 2; ++g) {
        int o = wn + g * 16 + ((l >> 4) & 1) * 8 + (l & 7);
        bRow[g] = (uint32_t)o * 512;
        bS[g] = (uint32_t)((o & 7) << 4);
    }
    const uint32_t a_k8b = ((l >> 4) & 1) * 16;
    const uint32_t b_k8b = ((l >> 3) & 1) * 16;

    const float* Xcur = Xin;
    const int* pm = (level0 == 0) ? perm : nullptr;
    int L = Lin, lvl = level0;

    for (int s = 0; s < nlev; ++s) {
        const int Lout = (L - 1) >> 1;
        float* Yout = (Lout == 1) ? outp : ((lvl & 1) ? bufB : bufA);
        const int ntiles = (Lout + 63) >> 6;

        // hoist per-level bias (4 nt blocks) into registers
        float bx[4], by[4];
        #pragma unroll
        for (int nt = 0; nt < 4; ++nt) {
            float2 bb = *(const float2*)&g_bias[lvl * CCH + wn + nt * 8 + (l & 3) * 2];
            bx[nt] = bb.x; by[nt] = bb.y;
        }

        for (int tile = blockIdx.x; tile < ntiles; tile += gridDim.x) {
            const int pbase = tile << 7;
            __syncthreads();   // protect X/stage smem across tiles/levels

            // ---- load X tile: 129 rows x 128 ch, split bf16 hi/lo ----
            for (int i = tid; i < 129 * 32; i += THREADS) {
                int row = i >> 5, c4 = i & 31;
                int pin = pbase + row; if (pin > L - 1) pin = L - 1;
                size_t srow = pm ? (size_t)pm[pin] : (size_t)pin;
                float4 v = *((const float4*)(Xcur + srow * CCH) + c4);
                __nv_bfloat16 h0 = __float2bfloat16_rn(v.x), h1 = __float2bfloat16_rn(v.y);
                __nv_bfloat16 h2 = __float2bfloat16_rn(v.z), h3 = __float2bfloat16_rn(v.w);
                __nv_bfloat16 l0 = __float2bfloat16_rn(v.x - __bfloat162float(h0));
                __nv_bfloat16 l1 = __float2bfloat16_rn(v.y - __bfloat162float(h1));
                __nv_bfloat16 l2 = __float2bfloat16_rn(v.z - __bfloat162float(h2));
                __nv_bfloat16 l3 = __float2bfloat16_rn(v.w - __bfloat162float(h3));
                __nv_bfloat162 hp0 = {h0, h1}, hp1 = {h2, h3};
                __nv_bfloat162 lp0 = {l0, l1}, lp1 = {l2, l3};
                uint32_t byte = (uint32_t)row * 256 +
                                (((uint32_t)c4 * 8) ^ (uint32_t)((row & 7) << 4));
                STS64(sb + SM_XH + byte, *(uint32_t*)&hp0, *(uint32_t*)&hp1);
                STS64(sb + SM_XL + byte, *(uint32_t*)&lp0, *(uint32_t*)&lp1);
            }
            __syncthreads();

            // ---- MMA: single kt loop, fragments reused across 3 products ----
            float acc[4][4][4];
            #pragma unroll
            for (int mt = 0; mt < 4; ++mt)
                #pragma unroll
                for (int nt = 0; nt < 4; ++nt)
                    #pragma unroll
                    for (int r = 0; r < 4; ++r) acc[mt][nt][r] = 0.f;

            #pragma unroll
            for (int kt = 0; kt < 16; ++kt) {
                const int tap = kt >> 3;
                const uint32_t chA = (uint32_t)(kt & 7) * 32 + a_k8b;
                const uint32_t chB = (uint32_t)kt * 32 + b_k8b;

                uint32_t Bh[4][2], Bl[4][2];
                ldx4(Bh[0][0], Bh[0][1], Bh[1][0], Bh[1][1], sb + SM_WH + bRow[0] + (chB ^ bS[0]));
                ldx4(Bh[2][0], Bh[2][1], Bh[3][0], Bh[3][1], sb + SM_WH + bRow[1] + (chB ^ bS[1]));
                ldx4(Bl[0][0], Bl[0][1], Bl[1][0], Bl[1][1], sb + SM_WL + bRow[0] + (chB ^ bS[0]));
                ldx4(Bl[2][0], Bl[2][1], Bl[3][0], Bl[3][1], sb + SM_WL + bRow[1] + (chB ^ bS[1]));

                #pragma unroll
                for (int mt = 0; mt < 4; ++mt) {
                    const uint32_t aoff = aAddr[mt][tap] + (chA ^ aS[mt][tap]);
                    uint32_t Ah[4], Al[4];
                    ldx4(Ah[0], Ah[1], Ah[2], Ah[3], sb + SM_XH + aoff);
                    ldx4(Al[0], Al[1], Al[2], Al[3], sb + SM_XL + aoff);
                    #pragma unroll
                    for (int nt = 0; nt < 4; ++nt) {
                        mma_bf16(acc[mt][nt], Ah, Bh[nt]);
                        mma_bf16(acc[mt][nt], Al, Bh[nt]);
                        mma_bf16(acc[mt][nt], Ah, Bl[nt]);
                    }
                }
            }

            // ---- epilogue: bias + leaky + pool(2) -> smem stage ----
            __syncthreads();   // MMA done before stage overwrites X smem
            const int r2 = l >> 2;
            const bool storer = ((r2 & 1) == 0);
            #pragma unroll
            for (int mt = 0; mt < 4; ++mt)
                #pragma unroll
                for (int nt = 0; nt < 4; ++nt) {
                    float* d = acc[mt][nt];
                    float v0 = d[0] + bx[nt], v1 = d[1] + by[nt];
                    float v2 = d[2] + bx[nt], v3 = d[3] + by[nt];
                    v0 = v0 >= 0.f ? v0 : 0.2f * v0;
                    v1 = v1 >= 0.f ? v1 : 0.2f * v1;
                    v2 = v2 >= 0.f ? v2 : 0.2f * v2;
                    v3 = v3 >= 0.f ? v3 : 0.2f * v3;
                    float u0 = fmaxf(v0, __shfl_xor_sync(0xffffffffu, v0, 4));
                    float u1 = fmaxf(v1, __shfl_xor_sync(0xffffffffu, v1, 4));
                    float u2 = fmaxf(v2, __shfl_xor_sync(0xffffffffu, v2, 4));
                    float u3 = fmaxf(v3, __shfl_xor_sync(0xffffffffu, v3, 4));
                    if (storer) {
                        const int o0 = wn + nt * 8 + (l & 3) * 2;
                        const int jl = (wm + mt * 16 + r2) >> 1;   // 0..63
                        *(float2*)&stagef[jl * STAGE_STRIDE + o0] = make_float2(u0, u1);
                        *(float2*)&stagef[(jl + 4) * STAGE_STRIDE + o0] = make_float2(u2, u3);
                    }
                }
            __syncthreads();

            // ---- coalesced store: 64 rows x 128 floats ----
            const int jbase = tile << 6;
            #pragma unroll
            for (int k = 0; k < 8; ++k) {
                int idx = tid + k * THREADS;           // 0..2047
                int row = idx >> 5, c4 = idx & 31;
                if (jbase + row < Lout) {
                    float4 v = *(const float4*)&stagef[row * STAGE_STRIDE + c4 * 4];
                    *(float4*)&Yout[(size_t)(jbase + row) * CCH + c4 * 4] = v;
                }
            }
        }
        Xcur = Yout;
        L = Lout;
        lvl++;
        pm = nullptr;
    }
}

// ---------------------------------------------------------------------------
extern "C" void kernel_launch(void* const* d_in, const int* in_sizes, int n_in,
                              void* d_out, int out_size) {
    const float* x     = (const float*)d_in[0];
    const float* depth = (const float*)d_in[1];
    const float* W     = (const float*)d_in[2];
    const float* b     = (const float*)d_in[3];
    const int*   perm  = (const int*)d_in[4];
    float* out = (float*)d_out;

    int N = in_sizes[0] / CCH;
    int nlev = 0;
    { int L = N; while (L > 1) { L = (L - 1) / 2; nlev++; } }

    cudaFuncSetAttribute((const void*)level_kernel,
                         cudaFuncAttributeMaxDynamicSharedMemorySize, SM_TOT);

    precompute_kernel<<<1, 256>>>(W, b, depth, nlev);

    float *bufA, *bufB;
    cudaGetSymbolAddress((void**)&bufA, g_bufA);
    cudaGetSymbolAddress((void**)&bufB, g_bufB);

    const float* cur = x;
    const int* permArg = perm;
    int L = N, level = 0;
    while (L > 1) {
        if (L <= 127) {
            int rem = 0;
            { int t = L; while (t > 1) { t = (t - 1) / 2; rem++; } }
            level_kernel<<<1, THREADS, SM_TOT>>>((const float*)cur, nullptr,
                                                 bufA, bufB, out, L, level, rem);
            break;
        }
        int Lout = (L - 1) / 2;
        int ntiles = (Lout + 63) / 64;
        int grid = ntiles < GRIDMAX ? ntiles : GRIDMAX;
        level_kernel<<<grid, THREADS, SM_TOT>>>((const float*)cur, permArg,
                                                bufA, bufB, out, L, level, 1);
        permArg = nullptr;
        cur = (Lout == 1) ? out : ((level & 1) ? bufB : bufA);
        L = Lout;
        level++;
    }
}

// round 5
// speedup vs baseline: 2.5593x; 1.2725x over previous
#include <cuda_runtime.h>
#include <cuda_bf16.h>
#include <stdint.h>

#define CCH 128
#define THREADS 256
#define GRIDMAX 152

// ---- device scratch ----
__device__ float    g_bias[32 * CCH];
__device__ uint32_t g_Wtm[2][CCH][128];     // [hi/lo][o][k/2] bf16x2 of Acat=[W0 W1]
__device__ float    g_bufA[262144 * 128];
__device__ float    g_bufB[131072 * 128];

// ---- SMEM layout (bytes) ----
// X double buffer: [buf][split] 65 rows x 256B = 16640 each
#define XBUF(buf, split) ((buf) * 33280 + (split) * 16640)
#define SM_W   66560                 // WH 65536 then WL 65536
#define SM_WH  SM_W
#define SM_WL  (SM_W + 65536)
#define SM_STAGE 197632              // 32 rows x 136 floats = 17408 B
#define SM_TOT  215040
#define STAGE_STRIDE 136

__device__ __forceinline__ uint32_t smem_u32(const void* p) {
    uint32_t a;
    asm("{ .reg .u64 t; cvta.to.shared.u64 t, %1; cvt.u32.u64 %0, t; }" : "=r"(a) : "l"(p));
    return a;
}
__device__ __forceinline__ void ldx4(uint32_t& r0, uint32_t& r1, uint32_t& r2, uint32_t& r3,
                                     uint32_t addr) {
    asm volatile("ldmatrix.sync.aligned.m8n8.x4.shared.b16 {%0,%1,%2,%3}, [%4];"
                 : "=r"(r0), "=r"(r1), "=r"(r2), "=r"(r3) : "r"(addr));
}
__device__ __forceinline__ void mma_bf16(float* d, const uint32_t* a, const uint32_t* b) {
    asm volatile("mma.sync.aligned.m16n8k16.row.col.f32.bf16.bf16.f32 "
                 "{%0,%1,%2,%3}, {%4,%5,%6,%7}, {%8,%9}, {%0,%1,%2,%3};"
                 : "+f"(d[0]), "+f"(d[1]), "+f"(d[2]), "+f"(d[3])
                 : "r"(a[0]), "r"(a[1]), "r"(a[2]), "r"(a[3]), "r"(b[0]), "r"(b[1]));
}
#define STS64(addr, x, y) \
    asm volatile("st.shared.v2.u32 [%0], {%1,%2};" :: "r"(addr), "r"(x), "r"(y) : "memory")

// convert one float4 to hi/lo bf16x2 pairs and store to both split planes
__device__ __forceinline__ void cvt_sts(float4 v, uint32_t dstH, uint32_t dstL) {
    __nv_bfloat16 h0 = __float2bfloat16_rn(v.x), h1 = __float2bfloat16_rn(v.y);
    __nv_bfloat16 h2 = __float2bfloat16_rn(v.z), h3 = __float2bfloat16_rn(v.w);
    __nv_bfloat16 l0 = __float2bfloat16_rn(v.x - __bfloat162float(h0));
    __nv_bfloat16 l1 = __float2bfloat16_rn(v.y - __bfloat162float(h1));
    __nv_bfloat16 l2 = __float2bfloat16_rn(v.z - __bfloat162float(h2));
    __nv_bfloat16 l3 = __float2bfloat16_rn(v.w - __bfloat162float(h3));
    __nv_bfloat162 hp0 = {h0, h1}, hp1 = {h2, h3};
    __nv_bfloat162 lp0 = {l0, l1}, lp1 = {l2, l3};
    STS64(dstH, *(uint32_t*)&hp0, *(uint32_t*)&hp1);
    STS64(dstL, *(uint32_t*)&lp0, *(uint32_t*)&lp1);
}

// ---------------------------------------------------------------------------
__global__ void precompute_kernel(const float* __restrict__ W,
                                  const float* __restrict__ b,
                                  const float* __restrict__ depth,
                                  int nlev) {
    int tid = threadIdx.x;
    for (int i = tid; i < 2 * CCH * 128; i += blockDim.x) {
        int s = i >> 14, o = (i >> 7) & 127, col = i & 127;
        uint32_t out = 0;
        #pragma unroll
        for (int h = 0; h < 2; ++h) {
            int c = 2 * col + h;
            float w = (c < 128) ? W[(size_t)o * 512 + c * 2]
                                : W[(size_t)o * 512 + (c - 128) * 2 + 1];
            __nv_bfloat16 hi = __float2bfloat16_rn(w);
            __nv_bfloat16 v = (s == 0) ? hi
                              : __float2bfloat16_rn(w - __bfloat162float(hi));
            uint16_t bits = *(uint16_t*)&v;
            out |= (uint32_t)bits << (16 * h);
        }
        g_Wtm[s][o][col] = out;
    }
    if (tid < CCH) {
        int o = tid;
        float ws[CCH];
        #pragma unroll 4
        for (int c = 0; c < CCH; ++c)
            ws[c] = W[(size_t)o * 512 + (128 + c) * 2 + 0] +
                    W[(size_t)o * 512 + (128 + c) * 2 + 1];
        for (int lev = 0; lev < nlev; ++lev) {
            float s = b[o];
            #pragma unroll 4
            for (int c = 0; c < CCH; ++c) s += ws[c] * depth[lev * CCH + c];
            g_bias[lev * CCH + o] = s;
        }
    }
}

// ---------------------------------------------------------------------------
// 64-position tiles, software-pipelined: prefetch next tile's X (LDG->regs)
// under the current tile's MMA, then cvt+STS into the other X buffer.
// D[p=64, o=128] per tile; epilogue bias+leaky+pool -> stage -> STG.128.
// ---------------------------------------------------------------------------
__global__ __launch_bounds__(THREADS, 1)
void level_kernel(const float* __restrict__ Xin, const int* __restrict__ perm,
                  float* bufA, float* bufB, float* outp,
                  int Lin, int level0, int nlev) {
    extern __shared__ char smem[];
    const uint32_t sb = smem_u32(smem);
    float* stagef = (float*)(smem + SM_STAGE);
    const int tid = threadIdx.x, l = tid & 31, wid = tid >> 5;
    const int wm = (wid >> 2) * 32, wn = (wid & 3) * 32;

    // ---- W -> smem once (swizzled rows of 512B) ----
    for (int i = tid; i < 2 * 128 * 64; i += THREADS) {
        int split = i >> 13, rem = i & 8191, o = rem >> 6, u = rem & 63;
        uint2 v = ((const uint2*)&g_Wtm[split][o][0])[u];
        uint32_t byte = (uint32_t)o * 512 + (((uint32_t)u * 8) ^ (uint32_t)((o & 7) << 4));
        STS64(sb + (split ? SM_WL : SM_WH) + byte, v.x, v.y);
    }

    // ---- per-lane fragment addresses ----
    const int arl = ((l >> 3) & 1) * 8 + (l & 7);
    uint32_t aAddr[2][2], aS[2][2];
    #pragma unroll
    for (int mt = 0; mt < 2; ++mt)
        #pragma unroll
        for (int tap = 0; tap < 2; ++tap) {
            int row = wm + mt * 16 + arl + tap;
            aAddr[mt][tap] = (uint32_t)row * 256;
            aS[mt][tap] = (uint32_t)((row & 7) << 4);
        }
    uint32_t bRow[2], bS[2];
    #pragma unroll
    for (int g = 0; g < 2; ++g) {
        int o = wn + g * 16 + ((l >> 4) & 1) * 8 + (l & 7);
        bRow[g] = (uint32_t)o * 512;
        bS[g] = (uint32_t)((o & 7) << 4);
    }
    const uint32_t a_k8b = ((l >> 4) & 1) * 16;
    const uint32_t b_k8b = ((l >> 3) & 1) * 16;
    // X load: thread (wid,l) owns rows wid+8*s, column l; swizzle constant/thread
    const uint32_t xswz = ((uint32_t)l * 8) ^ ((uint32_t)wid << 4);

    const float* Xcur = Xin;
    const int* pm = (level0 == 0) ? perm : nullptr;
    int L = Lin, lvl = level0;

    for (int s = 0; s < nlev; ++s) {
        const int Lout = (L - 1) >> 1;
        float* Yout = (Lout == 1) ? outp : ((lvl & 1) ? bufB : bufA);
        const int ntiles = (Lout + 31) >> 5;

        float bx[4], by[4];
        #pragma unroll
        for (int nt = 0; nt < 4; ++nt) {
            float2 bb = *(const float2*)&g_bias[lvl * CCH + wn + nt * 8 + (l & 3) * 2];
            bx[nt] = bb.x; by[nt] = bb.y;
        }

        // ---- prologue: load first tile into buf 0 ----
        int cur = 0;
        {
            const int pbase = blockIdx.x << 6;
            #pragma unroll
            for (int s9 = 0; s9 < 9; ++s9) {
                if (s9 == 8 && wid != 0) break;
                int row = s9 * 8 + wid;
                int pin = pbase + row; if (pin > L - 1) pin = L - 1;
                size_t srow = pm ? (size_t)pm[pin] : (size_t)pin;
                float4 v = *((const float4*)(Xcur + srow * CCH) + l);
                uint32_t byte = (uint32_t)row * 256 + xswz;
                cvt_sts(v, sb + XBUF(0, 0) + byte, sb + XBUF(0, 1) + byte);
            }
        }
        __syncthreads();

        for (int tile = blockIdx.x; tile < ntiles; tile += gridDim.x) {
            const int nexttile = tile + gridDim.x;
            const bool hasnext = nexttile < ntiles;

            // ---- 1. prefetch next tile's X into registers ----
            float4 pr[9];
            if (hasnext) {
                const int pbase = nexttile << 6;
                #pragma unroll
                for (int s9 = 0; s9 < 9; ++s9) {
                    if (s9 == 8 && wid != 0) break;
                    int row = s9 * 8 + wid;
                    int pin = pbase + row; if (pin > L - 1) pin = L - 1;
                    size_t srow = pm ? (size_t)pm[pin] : (size_t)pin;
                    pr[s9] = *((const float4*)(Xcur + srow * CCH) + l);
                }
            }

            // ---- 2. MMA from buf[cur] ----
            float acc[2][4][4];
            #pragma unroll
            for (int mt = 0; mt < 2; ++mt)
                #pragma unroll
                for (int nt = 0; nt < 4; ++nt)
                    #pragma unroll
                    for (int r = 0; r < 4; ++r) acc[mt][nt][r] = 0.f;

            const uint32_t xbH = sb + XBUF(cur, 0);
            const uint32_t xbL = sb + XBUF(cur, 1);
            #pragma unroll
            for (int kt = 0; kt < 16; ++kt) {
                const int tap = kt >> 3;
                const uint32_t chA = (uint32_t)(kt & 7) * 32 + a_k8b;
                const uint32_t chB = (uint32_t)kt * 32 + b_k8b;

                uint32_t Bh[4][2], Bl[4][2];
                ldx4(Bh[0][0], Bh[0][1], Bh[1][0], Bh[1][1], sb + SM_WH + bRow[0] + (chB ^ bS[0]));
                ldx4(Bh[2][0], Bh[2][1], Bh[3][0], Bh[3][1], sb + SM_WH + bRow[1] + (chB ^ bS[1]));
                ldx4(Bl[0][0], Bl[0][1], Bl[1][0], Bl[1][1], sb + SM_WL + bRow[0] + (chB ^ bS[0]));
                ldx4(Bl[2][0], Bl[2][1], Bl[3][0], Bl[3][1], sb + SM_WL + bRow[1] + (chB ^ bS[1]));

                #pragma unroll
                for (int mt = 0; mt < 2; ++mt) {
                    const uint32_t aoff = aAddr[mt][tap] + (chA ^ aS[mt][tap]);
                    uint32_t Ah[4], Al[4];
                    ldx4(Ah[0], Ah[1], Ah[2], Ah[3], xbH + aoff);
                    ldx4(Al[0], Al[1], Al[2], Al[3], xbL + aoff);
                    #pragma unroll
                    for (int nt = 0; nt < 4; ++nt) {
                        mma_bf16(acc[mt][nt], Ah, Bh[nt]);
                        mma_bf16(acc[mt][nt], Al, Bh[nt]);
                        mma_bf16(acc[mt][nt], Ah, Bl[nt]);
                    }
                }
            }

            // ---- 3. cvt + STS prefetched tile into buf[cur^1] ----
            if (hasnext) {
                const uint32_t dH = sb + XBUF(cur ^ 1, 0);
                const uint32_t dL = sb + XBUF(cur ^ 1, 1);
                #pragma unroll
                for (int s9 = 0; s9 < 9; ++s9) {
                    if (s9 == 8 && wid != 0) break;
                    uint32_t byte = (uint32_t)(s9 * 8 + wid) * 256 + xswz;
                    cvt_sts(pr[s9], dH + byte, dL + byte);
                }
            }

            // ---- 4. epilogue: bias + leaky + pool(2) -> stage ----
            const int r2 = l >> 2;
            const bool storer = ((r2 & 1) == 0);
            #pragma unroll
            for (int mt = 0; mt < 2; ++mt)
                #pragma unroll
                for (int nt = 0; nt < 4; ++nt) {
                    float* d = acc[mt][nt];
                    float v0 = d[0] + bx[nt], v1 = d[1] + by[nt];
                    float v2 = d[2] + bx[nt], v3 = d[3] + by[nt];
                    v0 = v0 >= 0.f ? v0 : 0.2f * v0;
                    v1 = v1 >= 0.f ? v1 : 0.2f * v1;
                    v2 = v2 >= 0.f ? v2 : 0.2f * v2;
                    v3 = v3 >= 0.f ? v3 : 0.2f * v3;
                    float u0 = fmaxf(v0, __shfl_xor_sync(0xffffffffu, v0, 4));
                    float u1 = fmaxf(v1, __shfl_xor_sync(0xffffffffu, v1, 4));
                    float u2 = fmaxf(v2, __shfl_xor_sync(0xffffffffu, v2, 4));
                    float u3 = fmaxf(v3, __shfl_xor_sync(0xffffffffu, v3, 4));
                    if (storer) {
                        const int o0 = wn + nt * 8 + (l & 3) * 2;
                        const int jl = (wm + mt * 16 + r2) >> 1;   // 0..31
                        *(float2*)&stagef[jl * STAGE_STRIDE + o0] = make_float2(u0, u1);
                        *(float2*)&stagef[(jl + 4) * STAGE_STRIDE + o0] = make_float2(u2, u3);
                    }
                }
            __syncthreads();   // STS (buf^1) + stage complete

            // ---- 5. coalesced store: 32 rows x 128 floats ----
            const int jbase = tile << 5;
            #pragma unroll
            for (int k = 0; k < 4; ++k) {
                int idx = tid + k * THREADS;           // 0..1023
                int row = idx >> 5, c4 = idx & 31;
                if (jbase + row < Lout) {
                    float4 v = *(const float4*)&stagef[row * STAGE_STRIDE + c4 * 4];
                    *(float4*)&Yout[(size_t)(jbase + row) * CCH + c4 * 4] = v;
                }
            }
            __syncthreads();   // stage free before next epilogue
            cur ^= 1;
        }
        Xcur = Yout;
        L = Lout;
        lvl++;
        pm = nullptr;
    }
}

// ---------------------------------------------------------------------------
extern "C" void kernel_launch(void* const* d_in, const int* in_sizes, int n_in,
                              void* d_out, int out_size) {
    const float* x     = (const float*)d_in[0];
    const float* depth = (const float*)d_in[1];
    const float* W     = (const float*)d_in[2];
    const float* b     = (const float*)d_in[3];
    const int*   perm  = (const int*)d_in[4];
    float* out = (float*)d_out;

    int N = in_sizes[0] / CCH;
    int nlev = 0;
    { int L = N; while (L > 1) { L = (L - 1) / 2; nlev++; } }

    cudaFuncSetAttribute((const void*)level_kernel,
                         cudaFuncAttributeMaxDynamicSharedMemorySize, SM_TOT);

    precompute_kernel<<<1, 256>>>(W, b, depth, nlev);

    float *bufA, *bufB;
    cudaGetSymbolAddress((void**)&bufA, g_bufA);
    cudaGetSymbolAddress((void**)&bufB, g_bufB);

    const float* cur = x;
    const int* permArg = perm;
    int L = N, level = 0;
    while (L > 1) {
        if (L <= 127) {
            int rem = 0;
            { int t = L; while (t > 1) { t = (t - 1) / 2; rem++; } }
            level_kernel<<<1, THREADS, SM_TOT>>>((const float*)cur, nullptr,
                                                 bufA, bufB, out, L, level, rem);
            break;
        }
        int Lout = (L - 1) / 2;
        int ntiles = (Lout + 31) / 32;
        int grid = ntiles < GRIDMAX ? ntiles : GRIDMAX;
        level_kernel<<<grid, THREADS, SM_TOT>>>((const float*)cur, permArg,
                                                bufA, bufB, out, L, level, 1);
        permArg = nullptr;
        cur = (Lout == 1) ? out : ((level & 1) ? bufB : bufA);
        L = Lout;
        level++;
    }
}